// round 8
// baseline (speedup 1.0000x reference)
#include <cuda_runtime.h>
#include <math.h>

#define NB    32
#define SL    20
#define DIM   256
#define BEAMW 4
#define G     128          // persistent grid (1 block/SM)
#define NT    512          // 4 teams x 128 threads
#define EPSC  1e-8f
#define LNEPS 1e-5f

// per-team smem: sA transposed [64 kk][68 pad] = 17408B + sB [64 kk][64] = 16384B
#define TEAM_BYTES 33792
#define SMEM_DYN   (4 * TEAM_BYTES)

#define NPOOL (NB * SL + 37 * NB * BEAMW)   // 640 token rows + 4736 reduce rows

// ---------------- static device scratch ----------------
__device__ float d_pool[NPOOL * DIM];        // [0,640): LN1 tokens; rest: reduce rows
__device__ int   d_tab[2][NB * BEAMW][SL];   // stack tables (pool slot ids)
__device__ int   d_p[2][NB * BEAMW];
__device__ int   d_q[2][NB * BEAMW];
__device__ int   d_asrc[2][128 * 3];         // per-row A descriptors: laster/last/cur
                                             // id>=0: pool row; -1: start; -2: zero
__device__ float d_cpart[3 * 128 * 256];     // conv partials (ks3)
__device__ float d_i1[2 * 128 * 1024];       // cell1 partials (ks2)
__device__ float d_c2[4 * 128 * 1024];       // cell2 partials (ks4)
__device__ float d_rs[128], d_ss[128];       // candidate log-scores
__device__ float d_bscore[NB * BEAMW];
__device__ unsigned g_cnt = 0;
__device__ unsigned g_gen = 0;

// ---------------- grid barrier ----------------
__device__ __forceinline__ void gbar() {
    __syncthreads();
    if (threadIdx.x == 0) {
        volatile unsigned* gen = &g_gen;
        unsigned my = *gen;
        __threadfence();
        if (atomicAdd(&g_cnt, 1u) == (unsigned)(G - 1)) {
            g_cnt = 0;
            __threadfence();
            *gen = my + 1u;
        } else {
            while (*gen == my) { }
        }
        __threadfence();
    }
    __syncthreads();
}

// ---------------- helpers ----------------
__device__ __forceinline__ float geluf(float x) {
    return 0.5f * x * (1.0f + erff(x * 0.7071067811865476f));
}
__device__ __forceinline__ float sigmoidf_(float x) {
    return 1.0f / (1.0f + expf(-x));
}

// 512 threads = two independent 256-thread halves; returns the half-sum
__device__ __forceinline__ float halfReduceSum(float v, float* sbuf) {
    int tid = threadIdx.x;
    #pragma unroll
    for (int o = 16; o > 0; o >>= 1) v += __shfl_down_sync(0xffffffffu, v, o);
    if ((tid & 31) == 0) sbuf[tid >> 5] = v;
    __syncthreads();
    int h = tid >> 8;
    float r = 0.f;
    #pragma unroll
    for (int w = 0; w < 8; w++) r += sbuf[h * 8 + w];
    __syncthreads();
    return r;
}

// ---------------- packed f32x2 FFMA ----------------
__device__ __forceinline__ unsigned long long pack2(float lo, float hi) {
    unsigned long long r;
    asm("mov.b64 %0, {%1, %2};" : "=l"(r) : "f"(lo), "f"(hi));
    return r;
}
__device__ __forceinline__ void fma2(unsigned long long& d, unsigned long long a,
                                     unsigned long long b) {
    asm("fma.rn.f32x2 %0, %1, %2, %0;" : "+l"(d) : "l"(a), "l"(b));
}
__device__ __forceinline__ void unpack2(unsigned long long v, float& lo, float& hi) {
    asm("mov.b64 {%0, %1}, %2;" : "=f"(lo), "=f"(hi) : "l"(v));
}

// ---------------- 64x64 tile GEMM job, K-slice 256 = 4 teams x 64 ----------------
// mode 0: A rows gathered from pool via descriptor seg ks (laster/last/cur).
// mode 1: A = gelu(i1_slab0 + i1_slab1 + gb[k]) at K-columns ks*256 + ...
// thread per team (128): rows w*16+(lane>>3)*4..+3, cols (lane&7)*8..+7.
__device__ void gemm_job(int mode, int ri, int ks,
                         const int* __restrict__ descr,
                         const float* __restrict__ start,
                         const float* __restrict__ gb,
                         const float* __restrict__ B, int ldb,
                         float* __restrict__ C, int ldc, char* dsm) {
    int tid  = threadIdx.x;
    int team = tid >> 7;
    int ttid = tid & 127;
    float* sA = (float*)(dsm + team * TEAM_BYTES);           // [64 kk][68]
    float* sB = (float*)(dsm + team * TEAM_BYTES + 17408);   // [64 kk][64]
    int kt = ks * 256 + team * 64;

    // stage A (transpose to [kk][row])
    {
        int k4 = ttid >> 3;            // 0..15
        int r0 = ttid & 7;
        int coff = team * 64 + k4 * 4; // 0..255 within the 256-seg
        #pragma unroll
        for (int p = 0; p < 8; p++) {
            int row = r0 + p * 8;
            int m = ri * 64 + row;
            float4 v;
            if (mode == 0) {
                int id = descr[m * 3 + ks];
                if (id >= 0)
                    v = *(const float4*)(d_pool + (size_t)id * DIM + coff);
                else if (id == -1)
                    v = *(const float4*)(start + coff);
                else
                    v = make_float4(0.f, 0.f, 0.f, 0.f);
            } else {
                const float* a0 = d_i1 + (size_t)m * 1024 + kt + k4 * 4;
                float4 x0 = *(const float4*)a0;
                float4 x1 = *(const float4*)(a0 + 131072);
                float4 bb = *(const float4*)(gb + kt + k4 * 4);
                v.x = geluf(x0.x + x1.x + bb.x);
                v.y = geluf(x0.y + x1.y + bb.y);
                v.z = geluf(x0.z + x1.z + bb.z);
                v.w = geluf(x0.w + x1.w + bb.w);
            }
            sA[(k4 * 4 + 0) * 68 + row] = v.x;
            sA[(k4 * 4 + 1) * 68 + row] = v.y;
            sA[(k4 * 4 + 2) * 68 + row] = v.z;
            sA[(k4 * 4 + 3) * 68 + row] = v.w;
        }
    }
    // stage B
    {
        int c4 = ttid & 15;
        #pragma unroll
        for (int p = 0; p < 8; p++) {
            int kloc = (ttid >> 4) + p * 8;
            *(float4*)(sB + kloc * 64 + c4 * 4) =
                *(const float4*)(B + (size_t)(kt + kloc) * ldb + c4 * 4);
        }
    }
    __syncthreads();

    int lane = ttid & 31, w = ttid >> 5;
    int arow = w * 16 + (lane >> 3) * 4;
    int bcol = (lane & 7) * 8;
    unsigned long long acc[16];
    #pragma unroll
    for (int i = 0; i < 16; i++) acc[i] = 0ull;

    #pragma unroll 8
    for (int kk = 0; kk < 64; kk++) {
        float4 av = *(const float4*)(sA + kk * 68 + arow);
        unsigned long long a0 = pack2(av.x, av.x);
        unsigned long long a1 = pack2(av.y, av.y);
        unsigned long long a2 = pack2(av.z, av.z);
        unsigned long long a3 = pack2(av.w, av.w);
        ulonglong2 b01 = *(const ulonglong2*)(sB + kk * 64 + bcol);
        ulonglong2 b23 = *(const ulonglong2*)(sB + kk * 64 + bcol + 4);
        fma2(acc[0],  a0, b01.x); fma2(acc[1],  a0, b01.y);
        fma2(acc[2],  a0, b23.x); fma2(acc[3],  a0, b23.y);
        fma2(acc[4],  a1, b01.x); fma2(acc[5],  a1, b01.y);
        fma2(acc[6],  a1, b23.x); fma2(acc[7],  a1, b23.y);
        fma2(acc[8],  a2, b01.x); fma2(acc[9],  a2, b01.y);
        fma2(acc[10], a2, b23.x); fma2(acc[11], a2, b23.y);
        fma2(acc[12], a3, b01.x); fma2(acc[13], a3, b01.y);
        fma2(acc[14], a3, b23.x); fma2(acc[15], a3, b23.y);
    }
    __syncthreads();

    float o[32];
    #pragma unroll
    for (int i = 0; i < 16; i++) unpack2(acc[i], o[2 * i], o[2 * i + 1]);

    if (team != 0) {
        float* cb = sB;
        #pragma unroll
        for (int j = 0; j < 32; j++) cb[j * 128 + ttid] = o[j];
    }
    __syncthreads();
    if (team == 0) {
        #pragma unroll
        for (int t = 1; t < 4; t++) {
            const float* cb = (const float*)(dsm + t * TEAM_BYTES + 17408);
            #pragma unroll
            for (int j = 0; j < 32; j++) o[j] += cb[j * 128 + ttid];
        }
        #pragma unroll
        for (int j = 0; j < 4; j++) {
            *(float4*)(C + (size_t)(arow + j) * ldc + bcol) =
                make_float4(o[8 * j], o[8 * j + 1], o[8 * j + 2], o[8 * j + 3]);
            *(float4*)(C + (size_t)(arow + j) * ldc + bcol + 4) =
                make_float4(o[8 * j + 4], o[8 * j + 5], o[8 * j + 6], o[8 * j + 7]);
        }
    }
    __syncthreads();
}

// ---------------- the persistent mega kernel ----------------
__global__ void __launch_bounds__(NT, 1)
mega(const float* __restrict__ sequence, const float* __restrict__ input_mask,
     const float* __restrict__ w_init, const float* __restrict__ b_init,
     const float* __restrict__ ln1_g, const float* __restrict__ ln1_b,
     const float* __restrict__ scorer_w, const float* __restrict__ scorer_b,
     const float* __restrict__ conv_w, const float* __restrict__ conv_b,
     const float* __restrict__ start,
     const float* __restrict__ wcell1_w, const float* __restrict__ wcell1_b,
     const float* __restrict__ wcell2_w, const float* __restrict__ wcell2_b,
     const float* __restrict__ ln2_g, const float* __restrict__ ln2_b,
     float* __restrict__ out) {
    extern __shared__ char dsm[];
    __shared__ float sred[16];
    __shared__ int   sparK[BEAMW], swrpos[BEAMW], swrval[BEAMW];

    int tid = threadIdx.x;
    int bid = blockIdx.x;
    int h   = tid >> 8;        // half id
    int col = tid & 255;

    // ---- init 1: pool tokens = LN1(sequence @ w_init + b_init); 2 rows/block ----
    {
        float* sX = (float*)dsm;   // [2][256]
        for (int job = bid; job < (NB * SL) / 2; job += G) {
            int row = job * 2 + h;
            sX[h * 256 + col] = sequence[(size_t)row * DIM + col];
            __syncthreads();
            float acc = 0.f;
            for (int i = 0; i < DIM; i++)
                acc += sX[h * 256 + i] * w_init[i * DIM + col];
            float y = acc + b_init[col];
            float s1 = halfReduceSum(y, sred);
            float s2 = halfReduceSum(y * y, sred);
            float m = s1 * (1.0f / DIM);
            float var = s2 * (1.0f / DIM) - m * m;
            d_pool[(size_t)row * DIM + col] =
                (y - m) * rsqrtf(var + LNEPS) * ln1_g[col] + ln1_b[col];
            __syncthreads();
        }
        // zero both descriptor buffers (padding rows -> pool row 0, harmless)
        if (bid == G - 1 && tid < 768) {
            d_asrc[0][tid] = 0;
            d_asrc[1][tid] = 0;
        }
    }
    gbar();

    // ---- init 2: stack tables + first descriptors (K=1, state buf=0) ----
    if (bid < NB && tid == 0) {
        int n = bid;
        d_tab[0][n * BEAMW][0] = n * SL + 0;
        d_tab[0][n * BEAMW][1] = n * SL + 1;
        int p = (input_mask[n * SL + 1] > 0.5f) ? 1 : 0;
        d_p[0][n * BEAMW] = p;
        d_q[0][n * BEAMW] = 0;
        d_asrc[0][n * 3 + 0] = (p >= 1) ? (n * SL + 0) : -1;   // laster (or START)
        d_asrc[0][n * 3 + 1] = n * SL + p;                      // last
        d_asrc[0][n * 3 + 2] = n * SL + 2;                      // cur (q=0)
    }
    gbar();

    int K = 1, buf = 0;
    for (int t = 2; t <= 2 * SL - 2; t++) {
        int newK = (2 * K < BEAMW) ? 2 * K : BEAMW;
        int nb2 = buf ^ 1;
        const int* dsc = d_asrc[buf];

        // ---- P1: cell1 partials (ks2: 64 jobs) + conv partials (ks3: 24 jobs) ----
        if (bid < 88) {
            if (bid < 64) {
                int ks = bid & 1, ct = (bid >> 1) & 15, ri = bid >> 5;
                gemm_job(0, ri, ks, dsc, start, nullptr,
                         wcell1_w + ct * 64, 1024,
                         d_i1 + (size_t)ks * 131072 + (size_t)ri * 64 * 1024 + ct * 64,
                         1024, dsm);
            } else {
                int j = bid - 64;              // 24 = ks3 x ct4 x ri2
                int ks = j % 3, r2 = j / 3;
                int ct = r2 & 3, ri = r2 >> 2;
                gemm_job(0, ri, ks, dsc, start, nullptr,
                         conv_w + ct * 64, 256,
                         d_cpart + (size_t)ks * 32768 + (size_t)ri * 64 * 256 + ct * 64,
                         256, dsm);
            }
        }
        gbar();

        // ---- P2: cell2 partials (ks4: 128 jobs) + distributed scores tail ----
        {
            int ks = bid & 3, ct = (bid >> 2) & 15, ri = bid >> 6;
            gemm_job(1, ri, ks, nullptr, nullptr, wcell1_b,
                     wcell2_w + ct * 64, 1024,
                     d_c2 + (size_t)ks * 131072 + (size_t)ri * 64 * 1024 + ct * 64,
                     1024, dsm);
        }
        if (bid < 64) {      // 2 scores per block (one per half)
            int m = 2 * bid + h;
            int valid = (m < NB * K);
            int mm = valid ? m : 0;
            float s = d_cpart[mm * 256 + col]
                    + d_cpart[32768 + mm * 256 + col]
                    + d_cpart[65536 + mm * 256 + col];
            float y = valid ? geluf(s + conv_b[col]) * scorer_w[col] : 0.f;
            float dot = halfReduceSum(y, sred);
            if (col == 0 && valid) {
                int n = mm / K, k = mm % K;
                float dec = sigmoidf_(dot + scorer_b[0]);
                int p = d_p[buf][n * BEAMW + k];
                int q = d_q[buf][n * BEAMW + k];
                float lp  = (p >= 1) ? 1.0f : 0.0f;
                float cmf = (q < SL - 2) ? input_mask[n * SL + 2 + q] : 0.0f;
                float bz  = ((lp == 0.0f) && (cmf == 0.0f)) ? 1.0f : 0.0f;
                float rs = cmf * dec + (1.0f - cmf);
                rs = lp * rs;
                rs = bz + (1.0f - bz) * rs;
                rs = logf(rs + EPSC);
                float ss = lp * (1.0f - dec) + (1.0f - lp);
                ss = cmf * ss;
                ss = (1.0f - bz) * ss;
                ss = logf(ss + EPSC);
                d_rs[mm] = rs;
                d_ss[mm] = ss;
            }
        }
        gbar();

        // ---- P3: top-k + tables + next descriptors (blocks 0-31)
        //          in parallel with compose (blocks 0-63, 2 rows each) ----
        if (bid < NB) {
            int n = bid;
            if (tid == 0) {
                int C2 = 2 * K;
                float sc[8];
                for (int c = 0; c < C2; c++)
                    sc[c] = (c < K) ? d_rs[n * K + c] : d_ss[n * K + (c - K)];
                int sel[BEAMW];
                if (C2 <= BEAMW) {
                    for (int s2 = 0; s2 < C2; s2++) { sel[s2] = s2; d_bscore[n * BEAMW + s2] = sc[s2]; }
                } else {
                    bool used[8];
                    for (int c = 0; c < C2; c++) used[c] = false;
                    for (int s2 = 0; s2 < BEAMW; s2++) {
                        int best = -1; float bv = 0.f;
                        for (int c = 0; c < C2; c++) {
                            if (used[c]) continue;
                            if (best < 0 || sc[c] > bv) { best = c; bv = sc[c]; }
                        }
                        used[best] = true;
                        sel[s2] = best;
                        d_bscore[n * BEAMW + s2] = bv;
                    }
                }
                for (int s2 = 0; s2 < newK; s2++) {
                    int c = sel[s2];
                    int isred = (c < K);
                    int k = isred ? c : (c - K);
                    int p = d_p[buf][n * BEAMW + k];
                    int q = d_q[buf][n * BEAMW + k];
                    int lp = (p >= 1);
                    float cmf = (q < SL - 2) ? input_mask[n * SL + 2 + q] : 0.0f;
                    int cm = (cmf > 0.5f);
                    int wr_pos = -1, newp = p, newq = q, wr_val = 0;
                    if (isred) {
                        if (lp) {
                            wr_pos = p - 1; newp = p - 1;
                            wr_val = NB * SL + (t - 2) * (NB * BEAMW) + n * BEAMW + k;
                        }
                    } else {
                        newq = q + 1;
                        if (cm) { wr_pos = p + 1; newp = p + 1; wr_val = n * SL + 2 + q; }
                    }
                    sparK[s2] = k; swrpos[s2] = wr_pos; swrval[s2] = wr_val;
                    d_p[nb2][n * BEAMW + s2] = newp;
                    d_q[nb2][n * BEAMW + s2] = newq;
                    // descriptors for next iteration (new table values, no copy wait)
                    const int* ot = d_tab[buf][n * BEAMW + k];
                    int laster = -1;
                    if (newp >= 1) {
                        int d = newp - 1;
                        laster = (d == wr_pos) ? wr_val : ot[d];
                    }
                    int lastv = (newp == wr_pos) ? wr_val : ot[newp];
                    int curv  = (newq < SL - 2) ? (n * SL + 2 + newq) : -2;
                    int m2 = n * newK + s2;
                    d_asrc[nb2][m2 * 3 + 0] = laster;
                    d_asrc[nb2][m2 * 3 + 1] = lastv;
                    d_asrc[nb2][m2 * 3 + 2] = curv;
                }
            }
            __syncthreads();
            // parallel table copy (newK*SL <= 80 entries)
            if (tid < newK * SL) {
                int s2 = tid / SL, d = tid % SL;
                int pk = sparK[s2];
                int v = d_tab[buf][n * BEAMW + pk][d];
                if (d == swrpos[s2]) v = swrval[s2];
                d_tab[nb2][n * BEAMW + s2][d] = v;
            }
            __syncthreads();
        }
        if (bid < 64) {      // compose: 2 rows per block (one per half)
            int m = 2 * bid + h;
            int valid = (m < NB * K);
            int mm = valid ? m : 0;
            const float* c0 = d_c2 + (size_t)mm * 1024;
            float seg[4];
            #pragma unroll
            for (int sg = 0; sg < 4; sg++) {
                seg[sg] = c0[sg * 256 + col]
                        + c0[131072 + sg * 256 + col]
                        + c0[262144 + sg * 256 + col]
                        + c0[393216 + sg * 256 + col]
                        + wcell2_b[sg * 256 + col];
            }
            int id1 = dsc[mm * 3 + 0];
            int id2 = dsc[mm * 3 + 1];
            float c1 = (id1 >= 0) ? d_pool[(size_t)id1 * DIM + col] : start[col];
            float c2v = d_pool[(size_t)id2 * DIM + col];
            float x = sigmoidf_(seg[0]) * c1
                    + sigmoidf_(seg[1]) * c2v
                    + sigmoidf_(seg[2]) * seg[3];
            float xm = valid ? x : 0.f;
            float s1 = halfReduceSum(xm, sred);
            float s2 = halfReduceSum(xm * xm, sred);
            if (valid) {
                float mn = s1 * (1.0f / DIM);
                float var = s2 * (1.0f / DIM) - mn * mn;
                int n = mm / K, k = mm % K;
                int rid = NB * SL + (t - 2) * (NB * BEAMW) + n * BEAMW + k;
                d_pool[(size_t)rid * DIM + col] =
                    (x - mn) * rsqrtf(var + LNEPS) * ln2_g[col] + ln2_b[col];
            }
        }
        gbar();
        buf ^= 1;
        K = newK;
    }

    // ---- final: softmax over beam scores, weighted top-of-stack sum ----
    if (bid < NB && h == 0) {
        int n = bid;
        float sc[BEAMW];
        float mx = -1e30f;
        #pragma unroll
        for (int k = 0; k < BEAMW; k++) {
            sc[k] = d_bscore[n * BEAMW + k];
            mx = fmaxf(mx, sc[k]);
        }
        float e[BEAMW], sum = 0.f;
        #pragma unroll
        for (int k = 0; k < BEAMW; k++) { e[k] = expf(sc[k] - mx); sum += e[k]; }
        float o = 0.f;
        #pragma unroll
        for (int k = 0; k < BEAMW; k++) {
            int p = d_p[buf][n * BEAMW + k];
            int slot = d_tab[buf][n * BEAMW + k][p];
            o += (e[k] / sum) * d_pool[(size_t)slot * DIM + col];
        }
        out[(size_t)n * DIM + col] = o;
    }
}

// ---------------- host launcher ----------------
extern "C" void kernel_launch(void* const* d_in, const int* in_sizes, int n_in,
                              void* d_out, int out_size) {
    const float* sequence   = (const float*)d_in[0];
    const float* input_mask = (const float*)d_in[1];
    const float* w_init     = (const float*)d_in[2];
    const float* b_init     = (const float*)d_in[3];
    const float* ln1_g      = (const float*)d_in[4];
    const float* ln1_b      = (const float*)d_in[5];
    const float* scorer_w   = (const float*)d_in[6];
    const float* scorer_b   = (const float*)d_in[7];
    const float* conv_w     = (const float*)d_in[8];
    const float* conv_b     = (const float*)d_in[9];
    const float* start      = (const float*)d_in[10];
    const float* wcell1_w   = (const float*)d_in[11];
    const float* wcell1_b   = (const float*)d_in[12];
    const float* wcell2_w   = (const float*)d_in[13];
    const float* wcell2_b   = (const float*)d_in[14];
    const float* ln2_g      = (const float*)d_in[15];
    const float* ln2_b      = (const float*)d_in[16];
    float* out = (float*)d_out;

    cudaFuncSetAttribute(mega, cudaFuncAttributeMaxDynamicSharedMemorySize, SMEM_DYN);
    mega<<<G, NT, SMEM_DYN>>>(sequence, input_mask, w_init, b_init, ln1_g, ln1_b,
                              scorer_w, scorer_b, conv_w, conv_b, start,
                              wcell1_w, wcell1_b, wcell2_w, wcell2_b, ln2_g, ln2_b, out);
}

// round 10
// speedup vs baseline: 1.6683x; 1.6683x over previous
#include <cuda_runtime.h>
#include <cuda_bf16.h>
#include <math.h>

#define NB    32
#define SL    20
#define DIM   256
#define BEAMW 4
#define G     128
#define NT    512
#define EPSC  1e-8f
#define LNEPS 1e-5f
#define NPOOL (NB * SL + 37 * NB * BEAMW)

// ---------------- static device scratch ----------------
__device__ float d_pool[NPOOL * DIM];
__device__ int   d_tab[2][NB * BEAMW][SL];
__device__ int   d_p[2][NB * BEAMW];
__device__ int   d_q[2][NB * BEAMW];
__device__ int   d_asrc[2][128 * 3];       // laster/last/cur: >=0 pool row, -1 start, -2 zero
__device__ float d_cpart[3 * 128 * 256];   // conv partials ks3
__device__ float d_i1[2 * 128 * 1024];     // cell1 partials ks2
__device__ float d_c2[4 * 128 * 1024];     // cell2 partials ks4
__device__ float d_rs[128], d_ss[128];
__device__ float d_bscore[NB * BEAMW];
// elementwise-converted bf16 hi/lo weights (same row-major layout as fp32 source)
__device__ __nv_bfloat16 d_w1h[512 * 1024],  d_w1l[512 * 1024];
__device__ __nv_bfloat16 d_w2h[1024 * 1024], d_w2l[1024 * 1024];
__device__ __nv_bfloat16 d_wch[768 * 256],   d_wcl[768 * 256];
__device__ unsigned g_cnt = 0, g_gen = 0;

// ---------------- grid barrier ----------------
__device__ __forceinline__ void gbar() {
    __syncthreads();
    if (threadIdx.x == 0) {
        volatile unsigned* gen = &g_gen;
        unsigned my = *gen;
        __threadfence();
        if (atomicAdd(&g_cnt, 1u) == (unsigned)(G - 1)) {
            g_cnt = 0; __threadfence(); *gen = my + 1u;
        } else {
            while (*gen == my) { }
        }
        __threadfence();
    }
    __syncthreads();
}

// ---------------- helpers ----------------
__device__ __forceinline__ float geluf(float x) {
    return 0.5f * x * (1.0f + erff(x * 0.7071067811865476f));
}
__device__ __forceinline__ float sigmoidf_(float x) {
    return 1.0f / (1.0f + expf(-x));
}
__device__ __forceinline__ float halfReduceSum(float v, float* sbuf) {
    int tid = threadIdx.x;
    #pragma unroll
    for (int o = 16; o > 0; o >>= 1) v += __shfl_down_sync(0xffffffffu, v, o);
    if ((tid & 31) == 0) sbuf[tid >> 5] = v;
    __syncthreads();
    int h = tid >> 8;
    float r = 0.f;
    #pragma unroll
    for (int w = 0; w < 8; w++) r += sbuf[h * 8 + w];
    __syncthreads();
    return r;
}
__device__ __forceinline__ unsigned smem_u32(const void* p) {
    unsigned a;
    asm("{ .reg .u64 t; cvta.to.shared.u64 t, %1; cvt.u32.u64 %0, t; }" : "=r"(a) : "l"(p));
    return a;
}
// 2 floats -> bf16x2 hi word + residual lo word
__device__ __forceinline__ void cvt2(float a, float b, unsigned& h, unsigned& l) {
    __nv_bfloat162 hh = __floats2bfloat162_rn(a, b);
    __nv_bfloat162 ll = __floats2bfloat162_rn(a - __bfloat162float(hh.x),
                                              b - __bfloat162float(hh.y));
    h = *reinterpret_cast<unsigned*>(&hh);
    l = *reinterpret_cast<unsigned*>(&ll);
}

#define LDM_X4(r, addr) \
    asm volatile("ldmatrix.sync.aligned.m8n8.x4.shared.b16 {%0,%1,%2,%3}, [%4];" \
        : "=r"((r)[0]), "=r"((r)[1]), "=r"((r)[2]), "=r"((r)[3]) : "r"(addr))
#define LDM_X4T(r, addr) \
    asm volatile("ldmatrix.sync.aligned.m8n8.x4.trans.shared.b16 {%0,%1,%2,%3}, [%4];" \
        : "=r"((r)[0]), "=r"((r)[1]), "=r"((r)[2]), "=r"((r)[3]) : "r"(addr))
#define MMA16816(d, a, b0, b1) \
    asm volatile("mma.sync.aligned.m16n8k16.row.col.f32.bf16.bf16.f32 " \
        "{%0,%1,%2,%3},{%4,%5,%6,%7},{%8,%9},{%0,%1,%2,%3};" \
        : "+f"((d)[0]), "+f"((d)[1]), "+f"((d)[2]), "+f"((d)[3]) \
        : "r"((a)[0]), "r"((a)[1]), "r"((a)[2]), "r"((a)[3]), "r"(b0), "r"(b1))

// ---------------- mma GEMM job: 64 rows x 64 cols x K256 ----------------
// amode 0: A rows from pool via dsc[seg=ks]; amode 1: A = gelu(i1_0+i1_1+gb).
// 16 warps: warp w -> rows mrow0=(w>>2)*16, cols ncol0=(w&3)*16 of the tile.
__device__ void gemm_mma(int amode, int ri, int ks,
                         const int* __restrict__ dsc, const float* __restrict__ start,
                         const float* __restrict__ gb,
                         const __nv_bfloat16* __restrict__ bH,
                         const __nv_bfloat16* __restrict__ bL, int Nw, int coloff,
                         float* __restrict__ C, int ldc,
                         __nv_bfloat16* sAh, __nv_bfloat16* sAl,
                         __nv_bfloat16* sBh, __nv_bfloat16* sBl) {
    int tid = threadIdx.x;
    int lane = tid & 31, w = tid >> 5;
    int mrow0 = (w >> 2) * 16, ncol0 = (w & 3) * 16;
    float acc[8];
    #pragma unroll
    for (int i = 0; i < 8; i++) acc[i] = 0.f;

    unsigned aBH = smem_u32(sAh) + ((mrow0 + (lane & 15)) * 72 + (lane >> 4) * 8) * 2;
    unsigned aBL = smem_u32(sAl) + ((mrow0 + (lane & 15)) * 72 + (lane >> 4) * 8) * 2;
    unsigned bBH = smem_u32(sBh) + ((lane & 15) * 72 + ncol0 + (lane >> 4) * 8) * 2;
    unsigned bBL = smem_u32(sBl) + ((lane & 15) * 72 + ncol0 + (lane >> 4) * 8) * 2;

    int r = tid >> 3;            // 0..63
    int e8 = (tid & 7) * 8;      // 0..56

    for (int c = 0; c < 4; c++) {
        // ---- stage A [64 rows][64 k] hi/lo ----
        {
            float x[8];
            int m = ri * 64 + r;
            if (amode == 0) {
                int id = dsc[m * 3 + ks];
                int colb = c * 64 + e8;
                if (id >= 0) {
                    const float* s = d_pool + (size_t)id * 256 + colb;
                    float4 v0 = *(const float4*)s, v1 = *(const float4*)(s + 4);
                    x[0] = v0.x; x[1] = v0.y; x[2] = v0.z; x[3] = v0.w;
                    x[4] = v1.x; x[5] = v1.y; x[6] = v1.z; x[7] = v1.w;
                } else if (id == -1) {
                    const float* s = start + colb;
                    float4 v0 = *(const float4*)s, v1 = *(const float4*)(s + 4);
                    x[0] = v0.x; x[1] = v0.y; x[2] = v0.z; x[3] = v0.w;
                    x[4] = v1.x; x[5] = v1.y; x[6] = v1.z; x[7] = v1.w;
                } else {
                    #pragma unroll
                    for (int j = 0; j < 8; j++) x[j] = 0.f;
                }
            } else {
                int kt = ks * 256 + c * 64 + e8;
                const float* pa = d_i1 + (size_t)m * 1024 + kt;
                float4 a0 = *(const float4*)pa,            a1 = *(const float4*)(pa + 4);
                float4 b0 = *(const float4*)(pa + 131072), b1 = *(const float4*)(pa + 131072 + 4);
                float4 g0 = *(const float4*)(gb + kt),     g1 = *(const float4*)(gb + kt + 4);
                x[0] = geluf(a0.x + b0.x + g0.x); x[1] = geluf(a0.y + b0.y + g0.y);
                x[2] = geluf(a0.z + b0.z + g0.z); x[3] = geluf(a0.w + b0.w + g0.w);
                x[4] = geluf(a1.x + b1.x + g1.x); x[5] = geluf(a1.y + b1.y + g1.y);
                x[6] = geluf(a1.z + b1.z + g1.z); x[7] = geluf(a1.w + b1.w + g1.w);
            }
            uint4 H, L;
            cvt2(x[0], x[1], H.x, L.x); cvt2(x[2], x[3], H.y, L.y);
            cvt2(x[4], x[5], H.z, L.z); cvt2(x[6], x[7], H.w, L.w);
            *(uint4*)(sAh + r * 72 + e8) = H;
            *(uint4*)(sAl + r * 72 + e8) = L;
        }
        // ---- stage B [64 k][64 n] hi/lo (elementwise-converted weights) ----
        {
            int kt = ks * 256 + c * 64 + r;
            size_t so = (size_t)kt * Nw + coloff + e8;
            *(uint4*)(sBh + r * 72 + e8) = *(const uint4*)(bH + so);
            *(uint4*)(sBl + r * 72 + e8) = *(const uint4*)(bL + so);
        }
        __syncthreads();
        #pragma unroll
        for (int kk = 0; kk < 4; kk++) {
            unsigned ah[4], al[4], bh[4], bl[4];
            LDM_X4(ah, aBH + kk * 32);          // +16 bf16 cols = 32 B
            LDM_X4(al, aBL + kk * 32);
            LDM_X4T(bh, bBH + kk * 2304);       // +16 k rows * 144 B
            LDM_X4T(bl, bBL + kk * 2304);
            MMA16816(acc,     ah, bh[0], bh[1]);
            MMA16816(acc,     al, bh[0], bh[1]);
            MMA16816(acc,     ah, bl[0], bl[1]);
            MMA16816(acc + 4, ah, bh[2], bh[3]);
            MMA16816(acc + 4, al, bh[2], bh[3]);
            MMA16816(acc + 4, ah, bl[2], bl[3]);
        }
        __syncthreads();
    }

    // ---- write C (local rows 0..63) ----
    int rw = mrow0 + (lane >> 2);
    int cw = ncol0 + (lane & 3) * 2;
    *(float2*)(C + (size_t)rw * ldc + cw)           = make_float2(acc[0], acc[1]);
    *(float2*)(C + (size_t)(rw + 8) * ldc + cw)     = make_float2(acc[2], acc[3]);
    *(float2*)(C + (size_t)rw * ldc + cw + 8)       = make_float2(acc[4], acc[5]);
    *(float2*)(C + (size_t)(rw + 8) * ldc + cw + 8) = make_float2(acc[6], acc[7]);
}

// ---------------- the persistent mega kernel ----------------
__global__ void __launch_bounds__(NT, 1)
mega(const float* __restrict__ sequence, const float* __restrict__ input_mask,
     const float* __restrict__ w_init, const float* __restrict__ b_init,
     const float* __restrict__ ln1_g, const float* __restrict__ ln1_b,
     const float* __restrict__ scorer_w, const float* __restrict__ scorer_b,
     const float* __restrict__ conv_w, const float* __restrict__ conv_b,
     const float* __restrict__ start,
     const float* __restrict__ wcell1_w, const float* __restrict__ wcell1_b,
     const float* __restrict__ wcell2_w, const float* __restrict__ wcell2_b,
     const float* __restrict__ ln2_g, const float* __restrict__ ln2_b,
     float* __restrict__ out) {
    __shared__ __align__(16) __nv_bfloat16 sAh[64 * 72], sAl[64 * 72];
    __shared__ __align__(16) __nv_bfloat16 sBh[64 * 72], sBl[64 * 72];
    __shared__ float sred[16];
    __shared__ int   sparK[BEAMW], swrpos[BEAMW], swrval[BEAMW];

    int tid = threadIdx.x;
    int bid = blockIdx.x;
    int h   = tid >> 8;
    int col = tid & 255;

    // ---- init 0: elementwise weight conversion to bf16 hi/lo ----
    {
        const int T1 = 512 * 1024, T2 = T1 + 1024 * 1024, T3 = T2 + 768 * 256;
        for (int idx = bid * NT + tid; idx < T3; idx += G * NT) {
            float v; __nv_bfloat16* ph; __nv_bfloat16* pl; int o;
            if (idx < T1)      { v = wcell1_w[idx];      ph = d_w1h; pl = d_w1l; o = idx; }
            else if (idx < T2) { o = idx - T1; v = wcell2_w[o]; ph = d_w2h; pl = d_w2l; }
            else               { o = idx - T2; v = conv_w[o];   ph = d_wch; pl = d_wcl; }
            __nv_bfloat16 hh = __float2bfloat16(v);
            ph[o] = hh;
            pl[o] = __float2bfloat16(v - __bfloat162float(hh));
        }
    }
    // ---- init 1: pool tokens = LN1(sequence @ w_init + b_init); 2 rows/block ----
    {
        float* sX = (float*)sAh;   // scratch
        for (int job = bid; job < (NB * SL) / 2; job += G) {
            int row = job * 2 + h;
            sX[h * 256 + col] = sequence[(size_t)row * DIM + col];
            __syncthreads();
            float acc = 0.f;
            for (int i = 0; i < DIM; i++)
                acc += sX[h * 256 + i] * w_init[i * DIM + col];
            float y = acc + b_init[col];
            float s1 = halfReduceSum(y, sred);
            float s2 = halfReduceSum(y * y, sred);
            float m = s1 * (1.0f / DIM);
            float var = s2 * (1.0f / DIM) - m * m;
            d_pool[(size_t)row * DIM + col] =
                (y - m) * rsqrtf(var + LNEPS) * ln1_g[col] + ln1_b[col];
            __syncthreads();
        }
        if (bid == G - 1 && tid < 768) { d_asrc[0][tid] = 0; d_asrc[1][tid] = 0; }
    }
    gbar();

    // ---- init 2: stack tables + first descriptors (K=1) ----
    if (bid < NB && tid == 0) {
        int n = bid;
        d_tab[0][n * BEAMW][0] = n * SL + 0;
        d_tab[0][n * BEAMW][1] = n * SL + 1;
        int p = (input_mask[n * SL + 1] > 0.5f) ? 1 : 0;
        d_p[0][n * BEAMW] = p;
        d_q[0][n * BEAMW] = 0;
        d_asrc[0][n * 3 + 0] = (p >= 1) ? (n * SL + 0) : -1;
        d_asrc[0][n * 3 + 1] = n * SL + p;
        d_asrc[0][n * 3 + 2] = n * SL + 2;
    }
    gbar();

    int K = 1, buf = 0;
    for (int t = 2; t <= 2 * SL - 2; t++) {
        int newK = (2 * K < BEAMW) ? 2 * K : BEAMW;
        int nb2 = buf ^ 1;
        const int* dsc = d_asrc[buf];

        // ---- P1: cell1 (ks2: 64 jobs) + conv (ks3: 24 jobs) ----
        if (bid < 88) {
            if (bid < 64) {
                int ks = bid & 1, ct = (bid >> 1) & 15, ri = bid >> 5;
                gemm_mma(0, ri, ks, dsc, start, nullptr,
                         d_w1h, d_w1l, 1024, ct * 64,
                         d_i1 + (size_t)ks * 131072 + (size_t)ri * 64 * 1024 + ct * 64,
                         1024, sAh, sAl, sBh, sBl);
            } else {
                int j = bid - 64;
                int ks = j % 3, r2 = j / 3;
                int ct = r2 & 3, ri = r2 >> 2;
                gemm_mma(0, ri, ks, dsc, start, nullptr,
                         d_wch, d_wcl, 256, ct * 64,
                         d_cpart + (size_t)ks * 32768 + (size_t)ri * 64 * 256 + ct * 64,
                         256, sAh, sAl, sBh, sBl);
            }
        }
        gbar();

        // ---- P2: cell2 (ks4: 128 jobs) + distributed scores tail ----
        {
            int ks = bid & 3, ct = (bid >> 2) & 15, ri = bid >> 6;
            gemm_mma(1, ri, ks, nullptr, nullptr, wcell1_b,
                     d_w2h, d_w2l, 1024, ct * 64,
                     d_c2 + (size_t)ks * 131072 + (size_t)ri * 64 * 1024 + ct * 64,
                     1024, sAh, sAl, sBh, sBl);
        }
        if (bid < 64) {
            int m = 2 * bid + h;
            int valid = (m < NB * K);
            int mm = valid ? m : 0;
            float s = d_cpart[mm * 256 + col]
                    + d_cpart[32768 + mm * 256 + col]
                    + d_cpart[65536 + mm * 256 + col];
            float y = valid ? geluf(s + conv_b[col]) * scorer_w[col] : 0.f;
            float dot = halfReduceSum(y, sred);
            if (col == 0 && valid) {
                int n = mm / K, k = mm % K;
                float dec = sigmoidf_(dot + scorer_b[0]);
                int p = d_p[buf][n * BEAMW + k];
                int q = d_q[buf][n * BEAMW + k];
                float lp  = (p >= 1) ? 1.0f : 0.0f;
                float cmf = (q < SL - 2) ? input_mask[n * SL + 2 + q] : 0.0f;
                float bz  = ((lp == 0.0f) && (cmf == 0.0f)) ? 1.0f : 0.0f;
                float rs = cmf * dec + (1.0f - cmf);
                rs = lp * rs; rs = bz + (1.0f - bz) * rs; rs = logf(rs + EPSC);
                float ss = lp * (1.0f - dec) + (1.0f - lp);
                ss = cmf * ss; ss = (1.0f - bz) * ss; ss = logf(ss + EPSC);
                d_rs[mm] = rs;
                d_ss[mm] = ss;
            }
        }
        gbar();

        // ---- P3: top-k + tables + descriptors (blocks 0-31) || compose (0-63) ----
        if (bid < NB) {
            int n = bid;
            if (tid == 0) {
                int C2 = 2 * K;
                float sc[8];
                for (int c = 0; c < C2; c++)
                    sc[c] = (c < K) ? d_rs[n * K + c] : d_ss[n * K + (c - K)];
                int sel[BEAMW];
                if (C2 <= BEAMW) {
                    for (int s2 = 0; s2 < C2; s2++) { sel[s2] = s2; d_bscore[n * BEAMW + s2] = sc[s2]; }
                } else {
                    bool used[8];
                    for (int c = 0; c < C2; c++) used[c] = false;
                    for (int s2 = 0; s2 < BEAMW; s2++) {
                        int best = -1; float bv = 0.f;
                        for (int c = 0; c < C2; c++) {
                            if (used[c]) continue;
                            if (best < 0 || sc[c] > bv) { best = c; bv = sc[c]; }
                        }
                        used[best] = true; sel[s2] = best;
                        d_bscore[n * BEAMW + s2] = bv;
                    }
                }
                for (int s2 = 0; s2 < newK; s2++) {
                    int c = sel[s2];
                    int isred = (c < K);
                    int k = isred ? c : (c - K);
                    int p = d_p[buf][n * BEAMW + k];
                    int q = d_q[buf][n * BEAMW + k];
                    int lp = (p >= 1);
                    float cmf = (q < SL - 2) ? input_mask[n * SL + 2 + q] : 0.0f;
                    int cm = (cmf > 0.5f);
                    int wr_pos = -1, newp = p, newq = q, wr_val = 0;
                    if (isred) {
                        if (lp) { wr_pos = p - 1; newp = p - 1;
                                  wr_val = NB * SL + (t - 2) * (NB * BEAMW) + n * BEAMW + k; }
                    } else {
                        newq = q + 1;
                        if (cm) { wr_pos = p + 1; newp = p + 1; wr_val = n * SL + 2 + q; }
                    }
                    sparK[s2] = k; swrpos[s2] = wr_pos; swrval[s2] = wr_val;
                    d_p[nb2][n * BEAMW + s2] = newp;
                    d_q[nb2][n * BEAMW + s2] = newq;
                    const int* ot = d_tab[buf][n * BEAMW + k];
                    int laster = -1;
                    if (newp >= 1) {
                        int d = newp - 1;
                        laster = (d == wr_pos) ? wr_val : ot[d];
                    }
                    int lastv = (newp == wr_pos) ? wr_val : ot[newp];
                    int curv  = (newq < SL - 2) ? (n * SL + 2 + newq) : -2;
                    int m2 = n * newK + s2;
                    d_asrc[nb2][m2 * 3 + 0] = laster;
                    d_asrc[nb2][m2 * 3 + 1] = lastv;
                    d_asrc[nb2][m2 * 3 + 2] = curv;
                }
            }
            __syncthreads();
            if (tid < newK * SL) {
                int s2 = tid / SL, d = tid % SL;
                int pk = sparK[s2];
                int v = d_tab[buf][n * BEAMW + pk][d];
                if (d == swrpos[s2]) v = swrval[s2];
                d_tab[nb2][n * BEAMW + s2][d] = v;
            }
            __syncthreads();
        }
        if (bid < 64) {      // compose: 2 rows per block (one per half)
            int m = 2 * bid + h;
            int valid = (m < NB * K);
            int mm = valid ? m : 0;
            const float* c0 = d_c2 + (size_t)mm * 1024;
            float seg[4];
            #pragma unroll
            for (int sg = 0; sg < 4; sg++) {
                seg[sg] = c0[sg * 256 + col]
                        + c0[131072 + sg * 256 + col]
                        + c0[262144 + sg * 256 + col]
                        + c0[393216 + sg * 256 + col]
                        + wcell2_b[sg * 256 + col];
            }
            int id1 = dsc[mm * 3 + 0];
            int id2 = dsc[mm * 3 + 1];
            float c1 = (id1 >= 0) ? d_pool[(size_t)id1 * DIM + col] : start[col];
            float c2v = d_pool[(size_t)id2 * DIM + col];
            float x = sigmoidf_(seg[0]) * c1
                    + sigmoidf_(seg[1]) * c2v
                    + sigmoidf_(seg[2]) * seg[3];
            float xm = valid ? x : 0.f;
            float s1 = halfReduceSum(xm, sred);
            float s2 = halfReduceSum(xm * xm, sred);
            if (valid) {
                float mn = s1 * (1.0f / DIM);
                float var = s2 * (1.0f / DIM) - mn * mn;
                int n = mm / K, k = mm % K;
                int rid = NB * SL + (t - 2) * (NB * BEAMW) + n * BEAMW + k;
                d_pool[(size_t)rid * DIM + col] =
                    (x - mn) * rsqrtf(var + LNEPS) * ln2_g[col] + ln2_b[col];
            }
        }
        gbar();
        buf ^= 1;
        K = newK;
    }

    // ---- final: softmax over beam scores, weighted top-of-stack sum ----
    if (bid < NB && h == 0) {
        int n = bid;
        float sc[BEAMW];
        float mx = -1e30f;
        #pragma unroll
        for (int k = 0; k < BEAMW; k++) { sc[k] = d_bscore[n * BEAMW + k]; mx = fmaxf(mx, sc[k]); }
        float e[BEAMW], sum = 0.f;
        #pragma unroll
        for (int k = 0; k < BEAMW; k++) { e[k] = expf(sc[k] - mx); sum += e[k]; }
        float o = 0.f;
        #pragma unroll
        for (int k = 0; k < BEAMW; k++) {
            int p = d_p[buf][n * BEAMW + k];
            int slot = d_tab[buf][n * BEAMW + k][p];
            o += (e[k] / sum) * d_pool[(size_t)slot * DIM + col];
        }
        out[(size_t)n * DIM + col] = o;
    }
}

// ---------------- host launcher ----------------
extern "C" void kernel_launch(void* const* d_in, const int* in_sizes, int n_in,
                              void* d_out, int out_size) {
    const float* sequence   = (const float*)d_in[0];
    const float* input_mask = (const float*)d_in[1];
    const float* w_init     = (const float*)d_in[2];
    const float* b_init     = (const float*)d_in[3];
    const float* ln1_g      = (const float*)d_in[4];
    const float* ln1_b      = (const float*)d_in[5];
    const float* scorer_w   = (const float*)d_in[6];
    const float* scorer_b   = (const float*)d_in[7];
    const float* conv_w     = (const float*)d_in[8];
    const float* conv_b     = (const float*)d_in[9];
    const float* start      = (const float*)d_in[10];
    const float* wcell1_w   = (const float*)d_in[11];
    const float* wcell1_b   = (const float*)d_in[12];
    const float* wcell2_w   = (const float*)d_in[13];
    const float* wcell2_b   = (const float*)d_in[14];
    const float* ln2_g      = (const float*)d_in[15];
    const float* ln2_b      = (const float*)d_in[16];
    float* out = (float*)d_out;

    mega<<<G, NT>>>(sequence, input_mask, w_init, b_init, ln1_g, ln1_b,
                    scorer_w, scorer_b, conv_w, conv_b, start,
                    wcell1_w, wcell1_b, wcell2_w, wcell2_b, ln2_g, ln2_b, out);
}

// round 11
// speedup vs baseline: 1.6852x; 1.0101x over previous
#include <cuda_runtime.h>
#include <cuda_bf16.h>
#include <math.h>

#define NB    32
#define SL    20
#define DIM   256
#define BEAMW 4
#define G     128
#define NT    512
#define EPSC  1e-8f
#define LNEPS 1e-5f
#define NPOOL (NB * SL + 37 * NB * BEAMW)

// dynamic smem: 8 buffers of 64*72 bf16 (9216 B): AH0 AH1 AL0 AL1 BH0 BH1 BL0 BL1
#define BUFB 9216
#define OAH(b) ((b) * BUFB)
#define OAL(b) (18432 + (b) * BUFB)
#define OBH(b) (36864 + (b) * BUFB)
#define OBL(b) (55296 + (b) * BUFB)
#define SMEM_DYN 73728

// ---------------- static device scratch ----------------
__device__ float d_pool[NPOOL * DIM];
__device__ int   d_tab[2][NB * BEAMW][SL];
__device__ int   d_p[2][NB * BEAMW];
__device__ int   d_q[2][NB * BEAMW];
__device__ int   d_asrc[2][128 * 3];       // laster/last/cur: >=0 pool row, -1 start, -2 zero
__device__ float d_cpart[3 * 128 * 256];   // conv partials ks3
__device__ float d_i1[2 * 128 * 1024];     // cell1 partials ks2
__device__ float d_c2[4 * 128 * 1024];     // cell2 partials ks4
__device__ float d_rs[128], d_ss[128];
__device__ float d_bscore[NB * BEAMW];
__device__ __nv_bfloat16 d_w1h[512 * 1024],  d_w1l[512 * 1024];
__device__ __nv_bfloat16 d_w2h[1024 * 1024], d_w2l[1024 * 1024];
__device__ __nv_bfloat16 d_wch[768 * 256],   d_wcl[768 * 256];
__device__ unsigned g_cnt = 0, g_gen = 0;

// ---------------- grid barrier ----------------
__device__ __forceinline__ void gbar() {
    __syncthreads();
    if (threadIdx.x == 0) {
        volatile unsigned* gen = &g_gen;
        unsigned my = *gen;
        __threadfence();
        if (atomicAdd(&g_cnt, 1u) == (unsigned)(G - 1)) {
            g_cnt = 0; __threadfence(); *gen = my + 1u;
        } else {
            while (*gen == my) { }
        }
        __threadfence();
    }
    __syncthreads();
}

// ---------------- helpers ----------------
__device__ __forceinline__ float geluf(float x) {
    return 0.5f * x * (1.0f + erff(x * 0.7071067811865476f));
}
__device__ __forceinline__ float sigmoidf_(float x) {
    return 1.0f / (1.0f + expf(-x));
}
__device__ __forceinline__ float halfReduceSum(float v, float* sbuf) {
    int tid = threadIdx.x;
    #pragma unroll
    for (int o = 16; o > 0; o >>= 1) v += __shfl_down_sync(0xffffffffu, v, o);
    if ((tid & 31) == 0) sbuf[tid >> 5] = v;
    __syncthreads();
    int h = tid >> 8;
    float r = 0.f;
    #pragma unroll
    for (int w = 0; w < 8; w++) r += sbuf[h * 8 + w];
    __syncthreads();
    return r;
}
__device__ __forceinline__ unsigned smem_u32(const void* p) {
    unsigned a;
    asm("{ .reg .u64 t; cvta.to.shared.u64 t, %1; cvt.u32.u64 %0, t; }" : "=r"(a) : "l"(p));
    return a;
}
__device__ __forceinline__ void cvt2(float a, float b, unsigned& h, unsigned& l) {
    __nv_bfloat162 hh = __floats2bfloat162_rn(a, b);
    __nv_bfloat162 ll = __floats2bfloat162_rn(a - __bfloat162float(hh.x),
                                              b - __bfloat162float(hh.y));
    h = *reinterpret_cast<unsigned*>(&hh);
    l = *reinterpret_cast<unsigned*>(&ll);
}

#define LDM_X4(r, addr) \
    asm volatile("ldmatrix.sync.aligned.m8n8.x4.shared.b16 {%0,%1,%2,%3}, [%4];" \
        : "=r"((r)[0]), "=r"((r)[1]), "=r"((r)[2]), "=r"((r)[3]) : "r"(addr))
#define LDM_X4T(r, addr) \
    asm volatile("ldmatrix.sync.aligned.m8n8.x4.trans.shared.b16 {%0,%1,%2,%3}, [%4];" \
        : "=r"((r)[0]), "=r"((r)[1]), "=r"((r)[2]), "=r"((r)[3]) : "r"(addr))
#define MMA16816(d, a, b0, b1) \
    asm volatile("mma.sync.aligned.m16n8k16.row.col.f32.bf16.bf16.f32 " \
        "{%0,%1,%2,%3},{%4,%5,%6,%7},{%8,%9},{%0,%1,%2,%3};" \
        : "+f"((d)[0]), "+f"((d)[1]), "+f"((d)[2]), "+f"((d)[3]) \
        : "r"((a)[0]), "r"((a)[1]), "r"((a)[2]), "r"((a)[3]), "r"(b0), "r"(b1))
#define CPA16(dst, src) \
    asm volatile("cp.async.cg.shared.global [%0], [%1], 16;" :: "r"(dst), "l"(src) : "memory")
#define CPA_COMMIT() asm volatile("cp.async.commit_group;" ::: "memory")
#define CPA_WAIT()   asm volatile("cp.async.wait_group 0;" ::: "memory")

// ---------------- pipelined mma GEMM job: 64 rows x 64 cols x K256 ----------------
// amode 0: A rows from pool via dsc[seg=ks]; amode 1: A = gelu(i1_0+i1_1+gb).
__device__ void gemm_mma(int amode, int ri, int ks,
                         const int* __restrict__ dsc, const float* __restrict__ start,
                         const float* __restrict__ gb,
                         const __nv_bfloat16* __restrict__ bH,
                         const __nv_bfloat16* __restrict__ bL, int Nw, int coloff,
                         float* __restrict__ C, int ldc,
                         char* dsb, unsigned sbase) {
    int tid = threadIdx.x;
    int lane = tid & 31, w = tid >> 5;
    int mrow0 = (w >> 2) * 16, ncol0 = (w & 3) * 16;
    float acc[8];
    #pragma unroll
    for (int i = 0; i < 8; i++) acc[i] = 0.f;

    int r = tid >> 3;            // 0..63
    int e8 = (tid & 7) * 8;      // 0..56
    int m = ri * 64 + r;
    unsigned stOff = (unsigned)(r * 72 + e8) * 2;   // staging store offset (bytes)
    unsigned aOff = ((mrow0 + (lane & 15)) * 72 + (lane >> 4) * 8) * 2;
    unsigned bOff = ((lane & 15) * 72 + ncol0 + (lane >> 4) * 8) * 2;

    // prefetch id once for amode 0
    int id = 0;
    if (amode == 0) id = dsc[m * 3 + ks];

    // A loader into regs
    float x[8];
    auto loadA = [&](int c, float* xr) {
        if (amode == 0) {
            int colb = c * 64 + e8;
            if (id >= 0) {
                const float* s = d_pool + (size_t)id * 256 + colb;
                float4 v0 = *(const float4*)s, v1 = *(const float4*)(s + 4);
                xr[0] = v0.x; xr[1] = v0.y; xr[2] = v0.z; xr[3] = v0.w;
                xr[4] = v1.x; xr[5] = v1.y; xr[6] = v1.z; xr[7] = v1.w;
            } else if (id == -1) {
                const float* s = start + c * 64 + e8;
                float4 v0 = *(const float4*)s, v1 = *(const float4*)(s + 4);
                xr[0] = v0.x; xr[1] = v0.y; xr[2] = v0.z; xr[3] = v0.w;
                xr[4] = v1.x; xr[5] = v1.y; xr[6] = v1.z; xr[7] = v1.w;
            } else {
                #pragma unroll
                for (int j = 0; j < 8; j++) xr[j] = 0.f;
            }
        } else {
            int kt = ks * 256 + c * 64 + e8;
            const float* pa = d_i1 + (size_t)m * 1024 + kt;
            float4 a0 = *(const float4*)pa,            a1 = *(const float4*)(pa + 4);
            float4 b0 = *(const float4*)(pa + 131072), b1 = *(const float4*)(pa + 131072 + 4);
            float4 g0 = *(const float4*)(gb + kt),     g1 = *(const float4*)(gb + kt + 4);
            xr[0] = geluf(a0.x + b0.x + g0.x); xr[1] = geluf(a0.y + b0.y + g0.y);
            xr[2] = geluf(a0.z + b0.z + g0.z); xr[3] = geluf(a0.w + b0.w + g0.w);
            xr[4] = geluf(a1.x + b1.x + g1.x); xr[5] = geluf(a1.y + b1.y + g1.y);
            xr[6] = geluf(a1.z + b1.z + g1.z); xr[7] = geluf(a1.w + b1.w + g1.w);
        }
    };
    auto storeA = [&](const float* xr, int b) {
        uint4 H, L;
        cvt2(xr[0], xr[1], H.x, L.x); cvt2(xr[2], xr[3], H.y, L.y);
        cvt2(xr[4], xr[5], H.z, L.z); cvt2(xr[6], xr[7], H.w, L.w);
        *(uint4*)(dsb + OAH(b) + stOff) = H;
        *(uint4*)(dsb + OAL(b) + stOff) = L;
    };
    auto cpB = [&](int c, int b) {
        int kt = ks * 256 + c * 64 + r;
        size_t so = (size_t)kt * Nw + coloff + e8;
        CPA16(sbase + OBH(b) + stOff, bH + so);
        CPA16(sbase + OBL(b) + stOff, bL + so);
    };

    // prologue: chunk 0 into buffer 0
    loadA(0, x);
    cpB(0, 0);
    CPA_COMMIT();
    storeA(x, 0);
    CPA_WAIT();
    __syncthreads();

    int p = 0;
    for (int c = 0; c < 4; c++) {
        float xn[8];
        if (c < 3) {
            loadA(c + 1, xn);          // gmem loads in flight during mma
            cpB(c + 1, p ^ 1);
            CPA_COMMIT();
        }
        unsigned aH = sbase + OAH(p) + aOff;
        unsigned aL = sbase + OAL(p) + aOff;
        unsigned bHs = sbase + OBH(p) + bOff;
        unsigned bLs = sbase + OBL(p) + bOff;
        #pragma unroll
        for (int kk = 0; kk < 4; kk++) {
            unsigned ah[4], al[4], bh[4], bl[4];
            LDM_X4(ah, aH + kk * 32);
            LDM_X4(al, aL + kk * 32);
            LDM_X4T(bh, bHs + kk * 2304);
            LDM_X4T(bl, bLs + kk * 2304);
            MMA16816(acc,     ah, bh[0], bh[1]);
            MMA16816(acc,     al, bh[0], bh[1]);
            MMA16816(acc,     ah, bl[0], bl[1]);
            MMA16816(acc + 4, ah, bh[2], bh[3]);
            MMA16816(acc + 4, al, bh[2], bh[3]);
            MMA16816(acc + 4, ah, bl[2], bl[3]);
        }
        if (c < 3) {
            storeA(xn, p ^ 1);
            CPA_WAIT();
        }
        __syncthreads();
        p ^= 1;
    }

    int rw = mrow0 + (lane >> 2);
    int cw = ncol0 + (lane & 3) * 2;
    *(float2*)(C + (size_t)rw * ldc + cw)           = make_float2(acc[0], acc[1]);
    *(float2*)(C + (size_t)(rw + 8) * ldc + cw)     = make_float2(acc[2], acc[3]);
    *(float2*)(C + (size_t)rw * ldc + cw + 8)       = make_float2(acc[4], acc[5]);
    *(float2*)(C + (size_t)(rw + 8) * ldc + cw + 8) = make_float2(acc[6], acc[7]);
}

// ---------------- the persistent mega kernel ----------------
__global__ void __launch_bounds__(NT, 1)
mega(const float* __restrict__ sequence, const float* __restrict__ input_mask,
     const float* __restrict__ w_init, const float* __restrict__ b_init,
     const float* __restrict__ ln1_g, const float* __restrict__ ln1_b,
     const float* __restrict__ scorer_w, const float* __restrict__ scorer_b,
     const float* __restrict__ conv_w, const float* __restrict__ conv_b,
     const float* __restrict__ start,
     const float* __restrict__ wcell1_w, const float* __restrict__ wcell1_b,
     const float* __restrict__ wcell2_w, const float* __restrict__ wcell2_b,
     const float* __restrict__ ln2_g, const float* __restrict__ ln2_b,
     float* __restrict__ out) {
    extern __shared__ char dsb[];
    unsigned sbase = smem_u32(dsb);
    __shared__ float sred[16];
    __shared__ int   sparK[BEAMW], swrpos[BEAMW], swrval[BEAMW];

    int tid = threadIdx.x;
    int bid = blockIdx.x;
    int h   = tid >> 8;
    int col = tid & 255;

    // ---- init 0: elementwise weight conversion to bf16 hi/lo ----
    {
        const int T1 = 512 * 1024, T2 = T1 + 1024 * 1024, T3 = T2 + 768 * 256;
        for (int idx = bid * NT + tid; idx < T3; idx += G * NT) {
            float v; __nv_bfloat16* ph; __nv_bfloat16* pl; int o;
            if (idx < T1)      { v = wcell1_w[idx];      ph = d_w1h; pl = d_w1l; o = idx; }
            else if (idx < T2) { o = idx - T1; v = wcell2_w[o]; ph = d_w2h; pl = d_w2l; }
            else               { o = idx - T2; v = conv_w[o];   ph = d_wch; pl = d_wcl; }
            __nv_bfloat16 hh = __float2bfloat16(v);
            ph[o] = hh;
            pl[o] = __float2bfloat16(v - __bfloat162float(hh));
        }
    }
    // ---- init 1: pool tokens = LN1(sequence @ w_init + b_init); 2 rows/block ----
    {
        float* sX = (float*)dsb;
        for (int job = bid; job < (NB * SL) / 2; job += G) {
            int row = job * 2 + h;
            sX[h * 256 + col] = sequence[(size_t)row * DIM + col];
            __syncthreads();
            float acc = 0.f;
            for (int i = 0; i < DIM; i++)
                acc += sX[h * 256 + i] * w_init[i * DIM + col];
            float y = acc + b_init[col];
            float s1 = halfReduceSum(y, sred);
            float s2 = halfReduceSum(y * y, sred);
            float m = s1 * (1.0f / DIM);
            float var = s2 * (1.0f / DIM) - m * m;
            d_pool[(size_t)row * DIM + col] =
                (y - m) * rsqrtf(var + LNEPS) * ln1_g[col] + ln1_b[col];
            __syncthreads();
        }
        if (bid == G - 1 && tid < 768) { d_asrc[0][tid] = 0; d_asrc[1][tid] = 0; }
    }
    gbar();

    // ---- init 2: stack tables + first descriptors (K=1) ----
    if (bid < NB && tid == 0) {
        int n = bid;
        d_tab[0][n * BEAMW][0] = n * SL + 0;
        d_tab[0][n * BEAMW][1] = n * SL + 1;
        int p = (input_mask[n * SL + 1] > 0.5f) ? 1 : 0;
        d_p[0][n * BEAMW] = p;
        d_q[0][n * BEAMW] = 0;
        d_asrc[0][n * 3 + 0] = (p >= 1) ? (n * SL + 0) : -1;
        d_asrc[0][n * 3 + 1] = n * SL + p;
        d_asrc[0][n * 3 + 2] = n * SL + 2;
    }
    gbar();

    int K = 1, buf = 0;
    for (int t = 2; t <= 2 * SL - 2; t++) {
        int newK = (2 * K < BEAMW) ? 2 * K : BEAMW;
        int nb2 = buf ^ 1;
        const int* dsc = d_asrc[buf];

        // ---- P1: cell1 (ks2: 64 jobs) + conv (ks3: 24 jobs) ----
        if (bid < 88) {
            if (bid < 64) {
                int ks = bid & 1, ct = (bid >> 1) & 15, ri = bid >> 5;
                gemm_mma(0, ri, ks, dsc, start, nullptr,
                         d_w1h, d_w1l, 1024, ct * 64,
                         d_i1 + (size_t)ks * 131072 + (size_t)ri * 64 * 1024 + ct * 64,
                         1024, dsb, sbase);
            } else {
                int j = bid - 64;
                int ks = j % 3, r2 = j / 3;
                int ct = r2 & 3, ri = r2 >> 2;
                gemm_mma(0, ri, ks, dsc, start, nullptr,
                         d_wch, d_wcl, 256, ct * 64,
                         d_cpart + (size_t)ks * 32768 + (size_t)ri * 64 * 256 + ct * 64,
                         256, dsb, sbase);
            }
        }
        gbar();

        // ---- P2: cell2 (ks4: 128 jobs) + distributed scores tail ----
        {
            int ks = bid & 3, ct = (bid >> 2) & 15, ri = bid >> 6;
            gemm_mma(1, ri, ks, nullptr, nullptr, wcell1_b,
                     d_w2h, d_w2l, 1024, ct * 64,
                     d_c2 + (size_t)ks * 131072 + (size_t)ri * 64 * 1024 + ct * 64,
                     1024, dsb, sbase);
        }
        if (bid < 64) {
            int m = 2 * bid + h;
            int valid = (m < NB * K);
            int mm = valid ? m : 0;
            float s = d_cpart[mm * 256 + col]
                    + d_cpart[32768 + mm * 256 + col]
                    + d_cpart[65536 + mm * 256 + col];
            float y = valid ? geluf(s + conv_b[col]) * scorer_w[col] : 0.f;
            float dot = halfReduceSum(y, sred);
            if (col == 0 && valid) {
                int n = mm / K, k = mm % K;
                float dec = sigmoidf_(dot + scorer_b[0]);
                int p = d_p[buf][n * BEAMW + k];
                int q = d_q[buf][n * BEAMW + k];
                float lp  = (p >= 1) ? 1.0f : 0.0f;
                float cmf = (q < SL - 2) ? input_mask[n * SL + 2 + q] : 0.0f;
                float bz  = ((lp == 0.0f) && (cmf == 0.0f)) ? 1.0f : 0.0f;
                float rs = cmf * dec + (1.0f - cmf);
                rs = lp * rs; rs = bz + (1.0f - bz) * rs; rs = logf(rs + EPSC);
                float ss = lp * (1.0f - dec) + (1.0f - lp);
                ss = cmf * ss; ss = (1.0f - bz) * ss; ss = logf(ss + EPSC);
                d_rs[mm] = rs;
                d_ss[mm] = ss;
            }
        }
        gbar();

        // ---- P3: top-k + tables + descriptors (blocks 0-31) || compose (0-63) ----
        if (bid < NB) {
            int n = bid;
            if (tid == 0) {
                int C2 = 2 * K;
                float sc[8];
                for (int c = 0; c < C2; c++)
                    sc[c] = (c < K) ? d_rs[n * K + c] : d_ss[n * K + (c - K)];
                int sel[BEAMW];
                if (C2 <= BEAMW) {
                    for (int s2 = 0; s2 < C2; s2++) { sel[s2] = s2; d_bscore[n * BEAMW + s2] = sc[s2]; }
                } else {
                    bool used[8];
                    for (int c = 0; c < C2; c++) used[c] = false;
                    for (int s2 = 0; s2 < BEAMW; s2++) {
                        int best = -1; float bv = 0.f;
                        for (int c = 0; c < C2; c++) {
                            if (used[c]) continue;
                            if (best < 0 || sc[c] > bv) { best = c; bv = sc[c]; }
                        }
                        used[best] = true; sel[s2] = best;
                        d_bscore[n * BEAMW + s2] = bv;
                    }
                }
                for (int s2 = 0; s2 < newK; s2++) {
                    int c = sel[s2];
                    int isred = (c < K);
                    int k = isred ? c : (c - K);
                    int p = d_p[buf][n * BEAMW + k];
                    int q = d_q[buf][n * BEAMW + k];
                    int lp = (p >= 1);
                    float cmf = (q < SL - 2) ? input_mask[n * SL + 2 + q] : 0.0f;
                    int cm = (cmf > 0.5f);
                    int wr_pos = -1, newp = p, newq = q, wr_val = 0;
                    if (isred) {
                        if (lp) { wr_pos = p - 1; newp = p - 1;
                                  wr_val = NB * SL + (t - 2) * (NB * BEAMW) + n * BEAMW + k; }
                    } else {
                        newq = q + 1;
                        if (cm) { wr_pos = p + 1; newp = p + 1; wr_val = n * SL + 2 + q; }
                    }
                    sparK[s2] = k; swrpos[s2] = wr_pos; swrval[s2] = wr_val;
                    d_p[nb2][n * BEAMW + s2] = newp;
                    d_q[nb2][n * BEAMW + s2] = newq;
                    const int* ot = d_tab[buf][n * BEAMW + k];
                    int laster = -1;
                    if (newp >= 1) {
                        int d = newp - 1;
                        laster = (d == wr_pos) ? wr_val : ot[d];
                    }
                    int lastv = (newp == wr_pos) ? wr_val : ot[newp];
                    int curv  = (newq < SL - 2) ? (n * SL + 2 + newq) : -2;
                    int m2 = n * newK + s2;
                    d_asrc[nb2][m2 * 3 + 0] = laster;
                    d_asrc[nb2][m2 * 3 + 1] = lastv;
                    d_asrc[nb2][m2 * 3 + 2] = curv;
                }
            }
            __syncthreads();
            if (tid < newK * SL) {
                int s2 = tid / SL, d = tid % SL;
                int pk = sparK[s2];
                int v = d_tab[buf][n * BEAMW + pk][d];
                if (d == swrpos[s2]) v = swrval[s2];
                d_tab[nb2][n * BEAMW + s2][d] = v;
            }
            __syncthreads();
        }
        if (bid < 64) {      // compose: 2 rows per block (one per half)
            int m = 2 * bid + h;
            int valid = (m < NB * K);
            int mm = valid ? m : 0;
            const float* c0 = d_c2 + (size_t)mm * 1024;
            float seg[4];
            #pragma unroll
            for (int sg = 0; sg < 4; sg++) {
                seg[sg] = c0[sg * 256 + col]
                        + c0[131072 + sg * 256 + col]
                        + c0[262144 + sg * 256 + col]
                        + c0[393216 + sg * 256 + col]
                        + wcell2_b[sg * 256 + col];
            }
            int id1 = dsc[mm * 3 + 0];
            int id2 = dsc[mm * 3 + 1];
            float c1 = (id1 >= 0) ? d_pool[(size_t)id1 * DIM + col] : start[col];
            float c2v = d_pool[(size_t)id2 * DIM + col];
            float x = sigmoidf_(seg[0]) * c1
                    + sigmoidf_(seg[1]) * c2v
                    + sigmoidf_(seg[2]) * seg[3];
            float xm = valid ? x : 0.f;
            float s1 = halfReduceSum(xm, sred);
            float s2 = halfReduceSum(xm * xm, sred);
            if (valid) {
                float mn = s1 * (1.0f / DIM);
                float var = s2 * (1.0f / DIM) - mn * mn;
                int n = mm / K, k = mm % K;
                int rid = NB * SL + (t - 2) * (NB * BEAMW) + n * BEAMW + k;
                d_pool[(size_t)rid * DIM + col] =
                    (x - mn) * rsqrtf(var + LNEPS) * ln2_g[col] + ln2_b[col];
            }
        }
        gbar();
        buf ^= 1;
        K = newK;
    }

    // ---- final: softmax over beam scores, weighted top-of-stack sum ----
    if (bid < NB && h == 0) {
        int n = bid;
        float sc[BEAMW];
        float mx = -1e30f;
        #pragma unroll
        for (int k = 0; k < BEAMW; k++) { sc[k] = d_bscore[n * BEAMW + k]; mx = fmaxf(mx, sc[k]); }
        float e[BEAMW], sum = 0.f;
        #pragma unroll
        for (int k = 0; k < BEAMW; k++) { e[k] = expf(sc[k] - mx); sum += e[k]; }
        float o = 0.f;
        #pragma unroll
        for (int k = 0; k < BEAMW; k++) {
            int p = d_p[buf][n * BEAMW + k];
            int slot = d_tab[buf][n * BEAMW + k][p];
            o += (e[k] / sum) * d_pool[(size_t)slot * DIM + col];
        }
        out[(size_t)n * DIM + col] = o;
    }
}

// ---------------- host launcher ----------------
extern "C" void kernel_launch(void* const* d_in, const int* in_sizes, int n_in,
                              void* d_out, int out_size) {
    const float* sequence   = (const float*)d_in[0];
    const float* input_mask = (const float*)d_in[1];
    const float* w_init     = (const float*)d_in[2];
    const float* b_init     = (const float*)d_in[3];
    const float* ln1_g      = (const float*)d_in[4];
    const float* ln1_b      = (const float*)d_in[5];
    const float* scorer_w   = (const float*)d_in[6];
    const float* scorer_b   = (const float*)d_in[7];
    const float* conv_w     = (const float*)d_in[8];
    const float* conv_b     = (const float*)d_in[9];
    const float* start      = (const float*)d_in[10];
    const float* wcell1_w   = (const float*)d_in[11];
    const float* wcell1_b   = (const float*)d_in[12];
    const float* wcell2_w   = (const float*)d_in[13];
    const float* wcell2_b   = (const float*)d_in[14];
    const float* ln2_g      = (const float*)d_in[15];
    const float* ln2_b      = (const float*)d_in[16];
    float* out = (float*)d_out;

    cudaFuncSetAttribute(mega, cudaFuncAttributeMaxDynamicSharedMemorySize, SMEM_DYN);
    mega<<<G, NT, SMEM_DYN>>>(sequence, input_mask, w_init, b_init, ln1_g, ln1_b,
                              scorer_w, scorer_b, conv_w, conv_b, start,
                              wcell1_w, wcell1_b, wcell2_w, wcell2_b, ln2_g, ln2_b, out);
}

// round 12
// speedup vs baseline: 1.7424x; 1.0339x over previous
#include <cuda_runtime.h>
#include <cuda_bf16.h>
#include <math.h>

#define NB    32
#define SL    20
#define DIM   256
#define BEAMW 4
#define G     128
#define NT    512
#define EPSC  1e-8f
#define LNEPS 1e-5f
#define NPOOL (NB * SL + 37 * NB * BEAMW)

// dynamic smem: 8 buffers of 64*72 bf16 (9216 B): AH0 AH1 AL0 AL1 BH0 BH1 BL0 BL1
#define BUFB 9216
#define OAH(b) ((b) * BUFB)
#define OAL(b) (18432 + (b) * BUFB)
#define OBH(b) (36864 + (b) * BUFB)
#define OBL(b) (55296 + (b) * BUFB)
#define SMEM_DYN 73728

// ---------------- static device scratch ----------------
__device__ float d_pool[NPOOL * DIM];
__device__ int   d_tab[2][NB * BEAMW][SL];
__device__ int   d_p[2][NB * BEAMW];
__device__ int   d_q[2][NB * BEAMW];
__device__ int   d_asrc[2][128 * 3];       // laster/last/cur: >=0 pool row, -1 start, -2 zero
__device__ float d_cpart[3 * 128 * 256];   // conv partials ks3
__device__ float d_i1[2 * 128 * 1024];     // cell1 partials ks2
__device__ float d_c2[4 * 128 * 1024];     // cell2 partials ks4
__device__ float d_rs[128], d_ss[128];
__device__ float d_bscore[NB * BEAMW];
__device__ __nv_bfloat16 d_w1h[512 * 1024],  d_w1l[512 * 1024];
__device__ __nv_bfloat16 d_w2h[1024 * 1024], d_w2l[1024 * 1024];
__device__ __nv_bfloat16 d_wch[768 * 256],   d_wcl[768 * 256];
// flag-array grid barrier state (zero-initialized; epochs are monotonic)
__device__ volatile unsigned g_flags[G];
__device__ volatile unsigned g_rel;

// ---------------- parallel flag-array grid barrier ----------------
// arrival: per-block own-word store (no atomic serialization)
// detection: block 0, 128 threads poll one flag each
// release: single word polled by other blocks
__device__ __forceinline__ void gbar(unsigned& ep) {
    __syncthreads();
    int tid = threadIdx.x;
    int bid = blockIdx.x;
    if (tid == 0) {
        __threadfence();
        g_flags[bid] = ep;
    }
    if (bid == 0) {
        if (tid < G) {
            while (g_flags[tid] < ep) { }
        }
        __syncthreads();
        if (tid == 0) {
            __threadfence();
            g_rel = ep;
        }
    } else {
        if (tid == 0) {
            while (g_rel < ep) { }
            __threadfence();
        }
    }
    __syncthreads();
    ep++;
}

// ---------------- helpers ----------------
__device__ __forceinline__ float geluf(float x) {
    return 0.5f * x * (1.0f + erff(x * 0.7071067811865476f));
}
__device__ __forceinline__ float sigmoidf_(float x) {
    return 1.0f / (1.0f + expf(-x));
}
__device__ __forceinline__ float halfReduceSum(float v, float* sbuf) {
    int tid = threadIdx.x;
    #pragma unroll
    for (int o = 16; o > 0; o >>= 1) v += __shfl_down_sync(0xffffffffu, v, o);
    if ((tid & 31) == 0) sbuf[tid >> 5] = v;
    __syncthreads();
    int h = tid >> 8;
    float r = 0.f;
    #pragma unroll
    for (int w = 0; w < 8; w++) r += sbuf[h * 8 + w];
    __syncthreads();
    return r;
}
__device__ __forceinline__ unsigned smem_u32(const void* p) {
    unsigned a;
    asm("{ .reg .u64 t; cvta.to.shared.u64 t, %1; cvt.u32.u64 %0, t; }" : "=r"(a) : "l"(p));
    return a;
}
__device__ __forceinline__ void cvt2(float a, float b, unsigned& h, unsigned& l) {
    __nv_bfloat162 hh = __floats2bfloat162_rn(a, b);
    __nv_bfloat162 ll = __floats2bfloat162_rn(a - __bfloat162float(hh.x),
                                              b - __bfloat162float(hh.y));
    h = *reinterpret_cast<unsigned*>(&hh);
    l = *reinterpret_cast<unsigned*>(&ll);
}

#define LDM_X4(r, addr) \
    asm volatile("ldmatrix.sync.aligned.m8n8.x4.shared.b16 {%0,%1,%2,%3}, [%4];" \
        : "=r"((r)[0]), "=r"((r)[1]), "=r"((r)[2]), "=r"((r)[3]) : "r"(addr))
#define LDM_X4T(r, addr) \
    asm volatile("ldmatrix.sync.aligned.m8n8.x4.trans.shared.b16 {%0,%1,%2,%3}, [%4];" \
        : "=r"((r)[0]), "=r"((r)[1]), "=r"((r)[2]), "=r"((r)[3]) : "r"(addr))
#define MMA16816(d, a, b0, b1) \
    asm volatile("mma.sync.aligned.m16n8k16.row.col.f32.bf16.bf16.f32 " \
        "{%0,%1,%2,%3},{%4,%5,%6,%7},{%8,%9},{%0,%1,%2,%3};" \
        : "+f"((d)[0]), "+f"((d)[1]), "+f"((d)[2]), "+f"((d)[3]) \
        : "r"((a)[0]), "r"((a)[1]), "r"((a)[2]), "r"((a)[3]), "r"(b0), "r"(b1))
#define CPA16(dst, src) \
    asm volatile("cp.async.cg.shared.global [%0], [%1], 16;" :: "r"(dst), "l"(src) : "memory")
#define CPA_COMMIT() asm volatile("cp.async.commit_group;" ::: "memory")
#define CPA_WAIT()   asm volatile("cp.async.wait_group 0;" ::: "memory")

// ---------------- pipelined mma GEMM job: 64 rows x 64 cols x K256 ----------------
// amode 0: A rows from pool via dsc[seg=ks]; amode 1: A = gelu(i1_0+i1_1+gb).
__device__ void gemm_mma(int amode, int ri, int ks,
                         const int* __restrict__ dsc, const float* __restrict__ start,
                         const float* __restrict__ gb,
                         const __nv_bfloat16* __restrict__ bH,
                         const __nv_bfloat16* __restrict__ bL, int Nw, int coloff,
                         float* __restrict__ C, int ldc,
                         char* dsb, unsigned sbase) {
    int tid = threadIdx.x;
    int lane = tid & 31, w = tid >> 5;
    int mrow0 = (w >> 2) * 16, ncol0 = (w & 3) * 16;
    float acc[8];
    #pragma unroll
    for (int i = 0; i < 8; i++) acc[i] = 0.f;

    int r = tid >> 3;            // 0..63
    int e8 = (tid & 7) * 8;      // 0..56
    int m = ri * 64 + r;
    unsigned stOff = (unsigned)(r * 72 + e8) * 2;
    unsigned aOff = ((mrow0 + (lane & 15)) * 72 + (lane >> 4) * 8) * 2;
    unsigned bOff = ((lane & 15) * 72 + ncol0 + (lane >> 4) * 8) * 2;

    int id = 0;
    if (amode == 0) id = dsc[m * 3 + ks];

    float x[8];
    auto loadA = [&](int c, float* xr) {
        if (amode == 0) {
            int colb = c * 64 + e8;
            if (id >= 0) {
                const float* s = d_pool + (size_t)id * 256 + colb;
                float4 v0 = *(const float4*)s, v1 = *(const float4*)(s + 4);
                xr[0] = v0.x; xr[1] = v0.y; xr[2] = v0.z; xr[3] = v0.w;
                xr[4] = v1.x; xr[5] = v1.y; xr[6] = v1.z; xr[7] = v1.w;
            } else if (id == -1) {
                const float* s = start + c * 64 + e8;
                float4 v0 = *(const float4*)s, v1 = *(const float4*)(s + 4);
                xr[0] = v0.x; xr[1] = v0.y; xr[2] = v0.z; xr[3] = v0.w;
                xr[4] = v1.x; xr[5] = v1.y; xr[6] = v1.z; xr[7] = v1.w;
            } else {
                #pragma unroll
                for (int j = 0; j < 8; j++) xr[j] = 0.f;
            }
        } else {
            int kt = ks * 256 + c * 64 + e8;
            const float* pa = d_i1 + (size_t)m * 1024 + kt;
            float4 a0 = *(const float4*)pa,            a1 = *(const float4*)(pa + 4);
            float4 b0 = *(const float4*)(pa + 131072), b1 = *(const float4*)(pa + 131072 + 4);
            float4 g0 = *(const float4*)(gb + kt),     g1 = *(const float4*)(gb + kt + 4);
            xr[0] = geluf(a0.x + b0.x + g0.x); xr[1] = geluf(a0.y + b0.y + g0.y);
            xr[2] = geluf(a0.z + b0.z + g0.z); xr[3] = geluf(a0.w + b0.w + g0.w);
            xr[4] = geluf(a1.x + b1.x + g1.x); xr[5] = geluf(a1.y + b1.y + g1.y);
            xr[6] = geluf(a1.z + b1.z + g1.z); xr[7] = geluf(a1.w + b1.w + g1.w);
        }
    };
    auto storeA = [&](const float* xr, int b) {
        uint4 H, L;
        cvt2(xr[0], xr[1], H.x, L.x); cvt2(xr[2], xr[3], H.y, L.y);
        cvt2(xr[4], xr[5], H.z, L.z); cvt2(xr[6], xr[7], H.w, L.w);
        *(uint4*)(dsb + OAH(b) + stOff) = H;
        *(uint4*)(dsb + OAL(b) + stOff) = L;
    };
    auto cpB = [&](int c, int b) {
        int kt = ks * 256 + c * 64 + r;
        size_t so = (size_t)kt * Nw + coloff + e8;
        CPA16(sbase + OBH(b) + stOff, bH + so);
        CPA16(sbase + OBL(b) + stOff, bL + so);
    };

    loadA(0, x);
    cpB(0, 0);
    CPA_COMMIT();
    storeA(x, 0);
    CPA_WAIT();
    __syncthreads();

    int p = 0;
    for (int c = 0; c < 4; c++) {
        float xn[8];
        if (c < 3) {
            loadA(c + 1, xn);
            cpB(c + 1, p ^ 1);
            CPA_COMMIT();
        }
        unsigned aH = sbase + OAH(p) + aOff;
        unsigned aL = sbase + OAL(p) + aOff;
        unsigned bHs = sbase + OBH(p) + bOff;
        unsigned bLs = sbase + OBL(p) + bOff;
        #pragma unroll
        for (int kk = 0; kk < 4; kk++) {
            unsigned ah[4], al[4], bh[4], bl[4];
            LDM_X4(ah, aH + kk * 32);
            LDM_X4(al, aL + kk * 32);
            LDM_X4T(bh, bHs + kk * 2304);
            LDM_X4T(bl, bLs + kk * 2304);
            MMA16816(acc,     ah, bh[0], bh[1]);
            MMA16816(acc,     al, bh[0], bh[1]);
            MMA16816(acc,     ah, bl[0], bl[1]);
            MMA16816(acc + 4, ah, bh[2], bh[3]);
            MMA16816(acc + 4, al, bh[2], bh[3]);
            MMA16816(acc + 4, ah, bl[2], bl[3]);
        }
        if (c < 3) {
            storeA(xn, p ^ 1);
            CPA_WAIT();
        }
        __syncthreads();
        p ^= 1;
    }

    int rw = mrow0 + (lane >> 2);
    int cw = ncol0 + (lane & 3) * 2;
    *(float2*)(C + (size_t)rw * ldc + cw)           = make_float2(acc[0], acc[1]);
    *(float2*)(C + (size_t)(rw + 8) * ldc + cw)     = make_float2(acc[2], acc[3]);
    *(float2*)(C + (size_t)rw * ldc + cw + 8)       = make_float2(acc[4], acc[5]);
    *(float2*)(C + (size_t)(rw + 8) * ldc + cw + 8) = make_float2(acc[6], acc[7]);
}

// ---------------- the persistent mega kernel ----------------
__global__ void __launch_bounds__(NT, 1)
mega(const float* __restrict__ sequence, const float* __restrict__ input_mask,
     const float* __restrict__ w_init, const float* __restrict__ b_init,
     const float* __restrict__ ln1_g, const float* __restrict__ ln1_b,
     const float* __restrict__ scorer_w, const float* __restrict__ scorer_b,
     const float* __restrict__ conv_w, const float* __restrict__ conv_b,
     const float* __restrict__ start,
     const float* __restrict__ wcell1_w, const float* __restrict__ wcell1_b,
     const float* __restrict__ wcell2_w, const float* __restrict__ wcell2_b,
     const float* __restrict__ ln2_g, const float* __restrict__ ln2_b,
     float* __restrict__ out) {
    extern __shared__ char dsb[];
    unsigned sbase = smem_u32(dsb);
    __shared__ float sred[16];
    __shared__ int   sparK[BEAMW], swrpos[BEAMW], swrval[BEAMW];

    int tid = threadIdx.x;
    int bid = blockIdx.x;
    int h   = tid >> 8;
    int col = tid & 255;
    unsigned ep = 1;

    // ---- init 0: elementwise weight conversion to bf16 hi/lo ----
    {
        const int T1 = 512 * 1024, T2 = T1 + 1024 * 1024, T3 = T2 + 768 * 256;
        for (int idx = bid * NT + tid; idx < T3; idx += G * NT) {
            float v; __nv_bfloat16* ph; __nv_bfloat16* pl; int o;
            if (idx < T1)      { v = wcell1_w[idx];      ph = d_w1h; pl = d_w1l; o = idx; }
            else if (idx < T2) { o = idx - T1; v = wcell2_w[o]; ph = d_w2h; pl = d_w2l; }
            else               { o = idx - T2; v = conv_w[o];   ph = d_wch; pl = d_wcl; }
            __nv_bfloat16 hh = __float2bfloat16(v);
            ph[o] = hh;
            pl[o] = __float2bfloat16(v - __bfloat162float(hh));
        }
    }
    // ---- init 1: pool tokens = LN1(sequence @ w_init + b_init); 2 rows/block ----
    {
        float* sX = (float*)dsb;
        for (int job = bid; job < (NB * SL) / 2; job += G) {
            int row = job * 2 + h;
            sX[h * 256 + col] = sequence[(size_t)row * DIM + col];
            __syncthreads();
            float acc = 0.f;
            for (int i = 0; i < DIM; i++)
                acc += sX[h * 256 + i] * w_init[i * DIM + col];
            float y = acc + b_init[col];
            float s1 = halfReduceSum(y, sred);
            float s2 = halfReduceSum(y * y, sred);
            float m = s1 * (1.0f / DIM);
            float var = s2 * (1.0f / DIM) - m * m;
            d_pool[(size_t)row * DIM + col] =
                (y - m) * rsqrtf(var + LNEPS) * ln1_g[col] + ln1_b[col];
            __syncthreads();
        }
        if (bid == G - 1 && tid < 768) { d_asrc[0][tid] = 0; d_asrc[1][tid] = 0; }
    }
    gbar(ep);

    // ---- init 2: stack tables + first descriptors (K=1) ----
    if (bid < NB && tid == 0) {
        int n = bid;
        d_tab[0][n * BEAMW][0] = n * SL + 0;
        d_tab[0][n * BEAMW][1] = n * SL + 1;
        int p = (input_mask[n * SL + 1] > 0.5f) ? 1 : 0;
        d_p[0][n * BEAMW] = p;
        d_q[0][n * BEAMW] = 0;
        d_asrc[0][n * 3 + 0] = (p >= 1) ? (n * SL + 0) : -1;
        d_asrc[0][n * 3 + 1] = n * SL + p;
        d_asrc[0][n * 3 + 2] = n * SL + 2;
    }
    gbar(ep);

    int K = 1, buf = 0;
    for (int t = 2; t <= 2 * SL - 2; t++) {
        int newK = (2 * K < BEAMW) ? 2 * K : BEAMW;
        int nb2 = buf ^ 1;
        const int* dsc = d_asrc[buf];

        // ---- P1: cell1 (ks2: 64 jobs) + conv (ks3: 24 jobs) ----
        if (bid < 88) {
            if (bid < 64) {
                int ks = bid & 1, ct = (bid >> 1) & 15, ri = bid >> 5;
                gemm_mma(0, ri, ks, dsc, start, nullptr,
                         d_w1h, d_w1l, 1024, ct * 64,
                         d_i1 + (size_t)ks * 131072 + (size_t)ri * 64 * 1024 + ct * 64,
                         1024, dsb, sbase);
            } else {
                int j = bid - 64;
                int ks = j % 3, r2 = j / 3;
                int ct = r2 & 3, ri = r2 >> 2;
                gemm_mma(0, ri, ks, dsc, start, nullptr,
                         d_wch, d_wcl, 256, ct * 64,
                         d_cpart + (size_t)ks * 32768 + (size_t)ri * 64 * 256 + ct * 64,
                         256, dsb, sbase);
            }
        }
        gbar(ep);

        // ---- P2: cell2 (ks4: 128 jobs) + distributed scores tail ----
        {
            int ks = bid & 3, ct = (bid >> 2) & 15, ri = bid >> 6;
            gemm_mma(1, ri, ks, nullptr, nullptr, wcell1_b,
                     d_w2h, d_w2l, 1024, ct * 64,
                     d_c2 + (size_t)ks * 131072 + (size_t)ri * 64 * 1024 + ct * 64,
                     1024, dsb, sbase);
        }
        if (bid < 64) {
            int m = 2 * bid + h;
            int valid = (m < NB * K);
            int mm = valid ? m : 0;
            float s = d_cpart[mm * 256 + col]
                    + d_cpart[32768 + mm * 256 + col]
                    + d_cpart[65536 + mm * 256 + col];
            float y = valid ? geluf(s + conv_b[col]) * scorer_w[col] : 0.f;
            float dot = halfReduceSum(y, sred);
            if (col == 0 && valid) {
                int n = mm / K, k = mm % K;
                float dec = sigmoidf_(dot + scorer_b[0]);
                int p = d_p[buf][n * BEAMW + k];
                int q = d_q[buf][n * BEAMW + k];
                float lp  = (p >= 1) ? 1.0f : 0.0f;
                float cmf = (q < SL - 2) ? input_mask[n * SL + 2 + q] : 0.0f;
                float bz  = ((lp == 0.0f) && (cmf == 0.0f)) ? 1.0f : 0.0f;
                float rs = cmf * dec + (1.0f - cmf);
                rs = lp * rs; rs = bz + (1.0f - bz) * rs; rs = logf(rs + EPSC);
                float ss = lp * (1.0f - dec) + (1.0f - lp);
                ss = cmf * ss; ss = (1.0f - bz) * ss; ss = logf(ss + EPSC);
                d_rs[mm] = rs;
                d_ss[mm] = ss;
            }
        }
        gbar(ep);

        // ---- P3: top-k + tables + descriptors (blocks 0-31) || compose (0-63) ----
        if (bid < NB) {
            int n = bid;
            if (tid == 0) {
                int C2 = 2 * K;
                float sc[8];
                for (int c = 0; c < C2; c++)
                    sc[c] = (c < K) ? d_rs[n * K + c] : d_ss[n * K + (c - K)];
                int sel[BEAMW];
                if (C2 <= BEAMW) {
                    for (int s2 = 0; s2 < C2; s2++) { sel[s2] = s2; d_bscore[n * BEAMW + s2] = sc[s2]; }
                } else {
                    bool used[8];
                    for (int c = 0; c < C2; c++) used[c] = false;
                    for (int s2 = 0; s2 < BEAMW; s2++) {
                        int best = -1; float bv = 0.f;
                        for (int c = 0; c < C2; c++) {
                            if (used[c]) continue;
                            if (best < 0 || sc[c] > bv) { best = c; bv = sc[c]; }
                        }
                        used[best] = true; sel[s2] = best;
                        d_bscore[n * BEAMW + s2] = bv;
                    }
                }
                for (int s2 = 0; s2 < newK; s2++) {
                    int c = sel[s2];
                    int isred = (c < K);
                    int k = isred ? c : (c - K);
                    int p = d_p[buf][n * BEAMW + k];
                    int q = d_q[buf][n * BEAMW + k];
                    int lp = (p >= 1);
                    float cmf = (q < SL - 2) ? input_mask[n * SL + 2 + q] : 0.0f;
                    int cm = (cmf > 0.5f);
                    int wr_pos = -1, newp = p, newq = q, wr_val = 0;
                    if (isred) {
                        if (lp) { wr_pos = p - 1; newp = p - 1;
                                  wr_val = NB * SL + (t - 2) * (NB * BEAMW) + n * BEAMW + k; }
                    } else {
                        newq = q + 1;
                        if (cm) { wr_pos = p + 1; newp = p + 1; wr_val = n * SL + 2 + q; }
                    }
                    sparK[s2] = k; swrpos[s2] = wr_pos; swrval[s2] = wr_val;
                    d_p[nb2][n * BEAMW + s2] = newp;
                    d_q[nb2][n * BEAMW + s2] = newq;
                    const int* ot = d_tab[buf][n * BEAMW + k];
                    int laster = -1;
                    if (newp >= 1) {
                        int d = newp - 1;
                        laster = (d == wr_pos) ? wr_val : ot[d];
                    }
                    int lastv = (newp == wr_pos) ? wr_val : ot[newp];
                    int curv  = (newq < SL - 2) ? (n * SL + 2 + newq) : -2;
                    int m2 = n * newK + s2;
                    d_asrc[nb2][m2 * 3 + 0] = laster;
                    d_asrc[nb2][m2 * 3 + 1] = lastv;
                    d_asrc[nb2][m2 * 3 + 2] = curv;
                }
            }
            __syncthreads();
            if (tid < newK * SL) {
                int s2 = tid / SL, d = tid % SL;
                int pk = sparK[s2];
                int v = d_tab[buf][n * BEAMW + pk][d];
                if (d == swrpos[s2]) v = swrval[s2];
                d_tab[nb2][n * BEAMW + s2][d] = v;
            }
            __syncthreads();
        }
        if (bid < 64) {
            int m = 2 * bid + h;
            int valid = (m < NB * K);
            int mm = valid ? m : 0;
            const float* c0 = d_c2 + (size_t)mm * 1024;
            float seg[4];
            #pragma unroll
            for (int sg = 0; sg < 4; sg++) {
                seg[sg] = c0[sg * 256 + col]
                        + c0[131072 + sg * 256 + col]
                        + c0[262144 + sg * 256 + col]
                        + c0[393216 + sg * 256 + col]
                        + wcell2_b[sg * 256 + col];
            }
            int id1 = dsc[mm * 3 + 0];
            int id2 = dsc[mm * 3 + 1];
            float c1 = (id1 >= 0) ? d_pool[(size_t)id1 * DIM + col] : start[col];
            float c2v = d_pool[(size_t)id2 * DIM + col];
            float x = sigmoidf_(seg[0]) * c1
                    + sigmoidf_(seg[1]) * c2v
                    + sigmoidf_(seg[2]) * seg[3];
            float xm = valid ? x : 0.f;
            float s1 = halfReduceSum(xm, sred);
            float s2 = halfReduceSum(xm * xm, sred);
            if (valid) {
                float mn = s1 * (1.0f / DIM);
                float var = s2 * (1.0f / DIM) - mn * mn;
                int n = mm / K, k = mm % K;
                int rid = NB * SL + (t - 2) * (NB * BEAMW) + n * BEAMW + k;
                d_pool[(size_t)rid * DIM + col] =
                    (x - mn) * rsqrtf(var + LNEPS) * ln2_g[col] + ln2_b[col];
            }
        }
        gbar(ep);
        buf ^= 1;
        K = newK;
    }

    // ---- final: softmax over beam scores, weighted top-of-stack sum ----
    if (bid < NB && h == 0) {
        int n = bid;
        float sc[BEAMW];
        float mx = -1e30f;
        #pragma unroll
        for (int k = 0; k < BEAMW; k++) { sc[k] = d_bscore[n * BEAMW + k]; mx = fmaxf(mx, sc[k]); }
        float e[BEAMW], sum = 0.f;
        #pragma unroll
        for (int k = 0; k < BEAMW; k++) { e[k] = expf(sc[k] - mx); sum += e[k]; }
        float o = 0.f;
        #pragma unroll
        for (int k = 0; k < BEAMW; k++) {
            int p = d_p[buf][n * BEAMW + k];
            int slot = d_tab[buf][n * BEAMW + k][p];
            o += (e[k] / sum) * d_pool[(size_t)slot * DIM + col];
        }
        out[(size_t)n * DIM + col] = o;
    }
}

// ---------------- host launcher ----------------
extern "C" void kernel_launch(void* const* d_in, const int* in_sizes, int n_in,
                              void* d_out, int out_size) {
    const float* sequence   = (const float*)d_in[0];
    const float* input_mask = (const float*)d_in[1];
    const float* w_init     = (const float*)d_in[2];
    const float* b_init     = (const float*)d_in[3];
    const float* ln1_g      = (const float*)d_in[4];
    const float* ln1_b      = (const float*)d_in[5];
    const float* scorer_w   = (const float*)d_in[6];
    const float* scorer_b   = (const float*)d_in[7];
    const float* conv_w     = (const float*)d_in[8];
    const float* conv_b     = (const float*)d_in[9];
    const float* start      = (const float*)d_in[10];
    const float* wcell1_w   = (const float*)d_in[11];
    const float* wcell1_b   = (const float*)d_in[12];
    const float* wcell2_w   = (const float*)d_in[13];
    const float* wcell2_b   = (const float*)d_in[14];
    const float* ln2_g      = (const float*)d_in[15];
    const float* ln2_b      = (const float*)d_in[16];
    float* out = (float*)d_out;

    cudaFuncSetAttribute(mega, cudaFuncAttributeMaxDynamicSharedMemorySize, SMEM_DYN);
    mega<<<G, NT, SMEM_DYN>>>(sequence, input_mask, w_init, b_init, ln1_g, ln1_b,
                              scorer_w, scorer_b, conv_w, conv_b, start,
                              wcell1_w, wcell1_b, wcell2_w, wcell2_b, ln2_g, ln2_b, out);
}